// round 15
// baseline (speedup 1.0000x reference)
#include <cuda_runtime.h>
#include <cstdint>

// ---------------------------------------------------------------------------
// Problem constants
// ---------------------------------------------------------------------------
#define BATCH 64
#define H_IN 480
#define W_IN 80
#define HID 256
#define T_STEPS 40
#define I_GRU 640           // 20 * 32
#define G3 768              // 3*HID
#define GX_N 1536           // both directions

// ---------------------------------------------------------------------------
// Scratch (static device allocations — no cudaMalloc anywhere)
// ---------------------------------------------------------------------------
__device__ float g_buf0[64 * 8  * 480 * 80];   // conv0 out
__device__ float g_buf1[64 * 16 * 480 * 80];   // conv1 out
__device__ float g_buf2[64 * 16 * 160 * 40];   // pool1 out
__device__ float g_buf3[64 * 16 * 160 * 40];   // conv2 out
__device__ float g_buf4[64 * 32 * 160 * 40];   // conv3 out
__device__ float g_x   [T_STEPS * BATCH * I_GRU];   // GRU input (T,B,I)
__device__ float g_gx  [T_STEPS * BATCH * GX_N];    // precomputed input gates
__device__ float g_wcat[GX_N * I_GRU];              // concat(w_ih_f, w_ih_b)
__device__ float g_bcat[GX_N];
__device__ float g_hA  [2 * BATCH * HID];
__device__ float g_hB  [2 * BATCH * HID];

// ---------------------------------------------------------------------------
// 3x3 conv + bias + ReLU, pad=1, stride=1, NCHW.
// One thread per output pixel, all COUT channels in registers.
// Input tile (with halo) + weights in shared memory.
// Weights laid out [tap][COUT] so per-tap channel reads are broadcast LDS.128.
// ---------------------------------------------------------------------------
template <int CIN, int COUT, int W, int TH, int H>
__global__ void conv3x3_relu(const float* __restrict__ in,
                             const float* __restrict__ wgt,
                             const float* __restrict__ bias,
                             float* __restrict__ outp)
{
    __shared__ __align__(16) float sIn[CIN][TH + 2][W + 2];
    __shared__ __align__(16) float sW[CIN * 9][COUT];
    __shared__ float sB[COUT];

    const int tx = threadIdx.x;            // 0..W-1
    const int ty = threadIdx.y;            // 0..TH-1
    const int tid = ty * W + tx;
    const int nthreads = W * TH;
    const int b  = blockIdx.y;
    const int h0 = blockIdx.x * TH;

    // weights: OIHW -> sW[ci*9 + tap][co]
    for (int i = tid; i < CIN * 9 * COUT; i += nthreads) {
        int co  = i % COUT;
        int tap = i / COUT;
        int ci  = tap / 9;
        int t9  = tap % 9;
        sW[tap][co] = wgt[(co * CIN + ci) * 9 + t9];
    }
    if (tid < COUT) sB[tid] = bias[tid];

    // input tile with 1-halo, zero padded
    const int TILE = CIN * (TH + 2) * (W + 2);
    for (int i = tid; i < TILE; i += nthreads) {
        int c  = i % (W + 2);
        int r  = (i / (W + 2)) % (TH + 2);
        int ci = i / ((W + 2) * (TH + 2));
        int gh = h0 + r - 1;
        int gw = c - 1;
        float v = 0.f;
        if (gh >= 0 && gh < H && gw >= 0 && gw < W)
            v = in[((size_t)(b * CIN + ci) * H + gh) * W + gw];
        sIn[ci][r][c] = v;
    }
    __syncthreads();

    float acc[COUT];
#pragma unroll
    for (int co = 0; co < COUT; co++) acc[co] = sB[co];

    for (int ci = 0; ci < CIN; ci++) {
#pragma unroll
        for (int ky = 0; ky < 3; ky++) {
#pragma unroll
            for (int kx = 0; kx < 3; kx++) {
                float v = sIn[ci][ty + ky][tx + kx];
                const float4* wv = (const float4*)&sW[ci * 9 + ky * 3 + kx][0];
#pragma unroll
                for (int q = 0; q < COUT / 4; q++) {
                    float4 w4 = wv[q];
                    acc[q * 4 + 0] = fmaf(v, w4.x, acc[q * 4 + 0]);
                    acc[q * 4 + 1] = fmaf(v, w4.y, acc[q * 4 + 1]);
                    acc[q * 4 + 2] = fmaf(v, w4.z, acc[q * 4 + 2]);
                    acc[q * 4 + 3] = fmaf(v, w4.w, acc[q * 4 + 3]);
                }
            }
        }
    }

#pragma unroll
    for (int co = 0; co < COUT; co++) {
        float r = acc[co] > 0.f ? acc[co] : 0.f;
        outp[((size_t)(b * COUT + co) * H + h0 + ty) * W + tx] = r;
    }
}

// ---------------------------------------------------------------------------
// maxpool 3x2 (stride = window): (64,16,480,80) -> (64,16,160,40)
// ---------------------------------------------------------------------------
__global__ void pool1_kernel(const float* __restrict__ in, float* __restrict__ outp)
{
    int i = blockIdx.x * blockDim.x + threadIdx.x;
    const int total = 64 * 16 * 160 * 40;
    if (i >= total) return;
    int wo = i % 40;
    int ho = (i / 40) % 160;
    int c  = (i / 6400) % 16;
    int b  = i / 102400;
    const float* base = in + (((size_t)(b * 16 + c) * 480) + ho * 3) * 80 + wo * 2;
    float m = base[0];
#pragma unroll
    for (int dh = 0; dh < 3; dh++)
#pragma unroll
        for (int dw = 0; dw < 2; dw++)
            m = fmaxf(m, base[dh * 80 + dw]);
    outp[i] = m;
}

// ---------------------------------------------------------------------------
// maxpool 4x2 + layout transform: (64,32,160,40) -> x[t][b][w*32 + c]
// (t = pooled h, w = pooled w).  Coalesced reads along w.
// ---------------------------------------------------------------------------
__global__ void pool2t_kernel(const float* __restrict__ in, float* __restrict__ xout)
{
    int i = blockIdx.x * blockDim.x + threadIdx.x;
    const int total = 64 * 32 * 40 * 20;
    if (i >= total) return;
    int w = i % 20;
    int t = (i / 20) % 40;
    int c = (i / 800) % 32;
    int b = i / 25600;
    const float* base = in + (((size_t)(b * 32 + c) * 160) + t * 4) * 40 + w * 2;
    float m = base[0];
#pragma unroll
    for (int dh = 0; dh < 4; dh++)
#pragma unroll
        for (int dw = 0; dw < 2; dw++)
            m = fmaxf(m, base[dh * 40 + dw]);
    xout[((size_t)(t * BATCH + b) * I_GRU) + w * 32 + c] = m;
}

// ---------------------------------------------------------------------------
// Concatenate input-gate weights/biases for both directions.
// ---------------------------------------------------------------------------
__global__ void prep_w_kernel(const float* __restrict__ wf, const float* __restrict__ wb,
                              const float* __restrict__ bf, const float* __restrict__ bb,
                              float* __restrict__ wcat, float* __restrict__ bcat)
{
    int i = blockIdx.x * blockDim.x + threadIdx.x;
    const int total = GX_N * I_GRU;
    if (i < total)
        wcat[i] = (i < G3 * I_GRU) ? wf[i] : wb[i - G3 * I_GRU];
    if (i < GX_N)
        bcat[i] = (i < G3) ? bf[i] : bb[i - G3];
}

__global__ void init_h_kernel(const float* __restrict__ h0, float* __restrict__ h)
{
    int i = blockIdx.x * blockDim.x + threadIdx.x;
    if (i < 2 * BATCH * HID) h[i] = h0[i];
}

// ---------------------------------------------------------------------------
// gx = x @ Wcat^T + bcat     (M=2560, N=1536, K=640, both K-contiguous "NT")
// 64x64x16 tiles, 256 threads, 4x4 micro-tile per thread, float4 smem reads.
// ---------------------------------------------------------------------------
__global__ void gemm_nt_kernel(const float* __restrict__ A,   // (2560, 640)
                               const float* __restrict__ B,   // (1536, 640)
                               const float* __restrict__ bias,
                               float* __restrict__ C)         // (2560, 1536)
{
    const int K = I_GRU;
    const int N = GX_N;
    __shared__ __align__(16) float As[16][64];
    __shared__ __align__(16) float Bs[16][64];

    const int bm = blockIdx.y;   // 0..39
    const int bn = blockIdx.x;   // 0..23
    const int t  = threadIdx.x;  // 0..255
    const int m0 = (t >> 4) * 4;
    const int n0 = (t & 15) * 4;

    const int lr = t >> 2;         // 0..63
    const int lk = (t & 3) * 4;    // 0,4,8,12
    const float* Arow = A + (size_t)(bm * 64 + lr) * K;
    const float* Brow = B + (size_t)(bn * 64 + lr) * K;

    float acc[4][4] = {};

    for (int k0 = 0; k0 < K; k0 += 16) {
        float4 av = *(const float4*)(Arow + k0 + lk);
        float4 bv = *(const float4*)(Brow + k0 + lk);
        As[lk + 0][lr] = av.x; As[lk + 1][lr] = av.y;
        As[lk + 2][lr] = av.z; As[lk + 3][lr] = av.w;
        Bs[lk + 0][lr] = bv.x; Bs[lk + 1][lr] = bv.y;
        Bs[lk + 2][lr] = bv.z; Bs[lk + 3][lr] = bv.w;
        __syncthreads();
#pragma unroll
        for (int k = 0; k < 16; k++) {
            float4 a  = *(const float4*)&As[k][m0];
            float4 bq = *(const float4*)&Bs[k][n0];
            acc[0][0] = fmaf(a.x, bq.x, acc[0][0]);
            acc[0][1] = fmaf(a.x, bq.y, acc[0][1]);
            acc[0][2] = fmaf(a.x, bq.z, acc[0][2]);
            acc[0][3] = fmaf(a.x, bq.w, acc[0][3]);
            acc[1][0] = fmaf(a.y, bq.x, acc[1][0]);
            acc[1][1] = fmaf(a.y, bq.y, acc[1][1]);
            acc[1][2] = fmaf(a.y, bq.z, acc[1][2]);
            acc[1][3] = fmaf(a.y, bq.w, acc[1][3]);
            acc[2][0] = fmaf(a.z, bq.x, acc[2][0]);
            acc[2][1] = fmaf(a.z, bq.y, acc[2][1]);
            acc[2][2] = fmaf(a.z, bq.z, acc[2][2]);
            acc[2][3] = fmaf(a.z, bq.w, acc[2][3]);
            acc[3][0] = fmaf(a.w, bq.x, acc[3][0]);
            acc[3][1] = fmaf(a.w, bq.y, acc[3][1]);
            acc[3][2] = fmaf(a.w, bq.z, acc[3][2]);
            acc[3][3] = fmaf(a.w, bq.w, acc[3][3]);
        }
        __syncthreads();
    }

    const int cm = bm * 64 + m0;
    const int cn = bn * 64 + n0;
    float b4[4];
#pragma unroll
    for (int j = 0; j < 4; j++) b4[j] = bias[cn + j];
#pragma unroll
    for (int i = 0; i < 4; i++)
#pragma unroll
        for (int j = 0; j < 4; j++)
            C[(size_t)(cm + i) * N + cn + j] = acc[i][j] + b4[j];
}

// ---------------------------------------------------------------------------
// One GRU time step, both directions fused.
// 128 blocks x 256 threads: block = (dir, 8-batch group, 32-j group).
// Thread computes full r/z/n for one (b, j): 3 dot products of length 256,
// h in smem (broadcast), W_hh streamed from L2.
// ---------------------------------------------------------------------------
__global__ void gru_step_kernel(const float* __restrict__ gx,
                                const float* __restrict__ whh_f,
                                const float* __restrict__ whh_b,
                                const float* __restrict__ bhh_f,
                                const float* __restrict__ bhh_b,
                                const float* __restrict__ h_in,
                                float* __restrict__ h_out,
                                float* __restrict__ outp,      // (B,T,512)
                                float* __restrict__ hid_out,   // (2,B,256)
                                int step)
{
    const int x   = blockIdx.x;      // 0..127
    const int dir = x >> 6;
    const int rem = x & 63;
    const int bg  = rem >> 3;        // 0..7
    const int jg  = rem & 7;         // 0..7
    const int tid = threadIdx.x;
    const int bl  = tid >> 5;        // 0..7
    const int jl  = tid & 31;
    const int b   = bg * 8 + bl;
    const int j   = jg * 32 + jl;

    __shared__ __align__(16) float sh[8][HID];
    const float* hbase = h_in + (size_t)dir * BATCH * HID + (size_t)bg * 8 * HID;
    for (int i = tid; i < 8 * HID; i += 256)
        sh[i >> 8][i & 255] = hbase[i];
    __syncthreads();

    const float* whh = dir ? whh_b : whh_f;
    const float* bhh = dir ? bhh_b : bhh_f;

    const float4* hv = (const float4*)sh[bl];
    const float4* wr = (const float4*)(whh + (size_t)j * HID);
    const float4* wz = (const float4*)(whh + (size_t)(j + 256) * HID);
    const float4* wn = (const float4*)(whh + (size_t)(j + 512) * HID);

    float ar = 0.f, az = 0.f, an = 0.f;
#pragma unroll 8
    for (int k = 0; k < HID / 4; k++) {
        float4 h4 = hv[k];
        float4 r4 = wr[k];
        float4 z4 = wz[k];
        float4 n4 = wn[k];
        ar = fmaf(h4.x, r4.x, ar); ar = fmaf(h4.y, r4.y, ar);
        ar = fmaf(h4.z, r4.z, ar); ar = fmaf(h4.w, r4.w, ar);
        az = fmaf(h4.x, z4.x, az); az = fmaf(h4.y, z4.y, az);
        az = fmaf(h4.z, z4.z, az); az = fmaf(h4.w, z4.w, az);
        an = fmaf(h4.x, n4.x, an); an = fmaf(h4.y, n4.y, an);
        an = fmaf(h4.z, n4.z, an); an = fmaf(h4.w, n4.w, an);
    }

    const int t = dir ? (T_STEPS - 1 - step) : step;
    const float* gxr = gx + (size_t)(t * BATCH + b) * GX_N + dir * G3;
    float xr = gxr[j];
    float xz = gxr[256 + j];
    float xn = gxr[512 + j];

    float hr = ar + bhh[j];
    float hz = az + bhh[256 + j];
    float hn = an + bhh[512 + j];

    float r = 1.f / (1.f + __expf(-(xr + hr)));
    float z = 1.f / (1.f + __expf(-(xz + hz)));
    float n = tanhf(xn + r * hn);

    float hold = sh[bl][j];
    float hnew = (1.f - z) * n + z * hold;

    h_out[(size_t)dir * BATCH * HID + (size_t)b * HID + j] = hnew;
    outp[((size_t)b * T_STEPS + t) * 512 + dir * HID + j] = hnew;
    if (step == T_STEPS - 1)
        hid_out[(size_t)dir * BATCH * HID + (size_t)b * HID + j] = hnew;
}

// ---------------------------------------------------------------------------
// Launch
// ---------------------------------------------------------------------------
extern "C" void kernel_launch(void* const* d_in, const int* in_sizes, int n_in,
                              void* d_out, int out_size)
{
    const float* img  = (const float*)d_in[0];
    const float* hid0 = (const float*)d_in[1];
    const float* c0w  = (const float*)d_in[2];
    const float* c0b  = (const float*)d_in[3];
    const float* c1w  = (const float*)d_in[4];
    const float* c1b  = (const float*)d_in[5];
    const float* c2w  = (const float*)d_in[6];
    const float* c2b  = (const float*)d_in[7];
    const float* c3w  = (const float*)d_in[8];
    const float* c3b  = (const float*)d_in[9];
    const float* wihf = (const float*)d_in[10];
    const float* whhf = (const float*)d_in[11];
    const float* bihf = (const float*)d_in[12];
    const float* bhhf = (const float*)d_in[13];
    const float* wihb = (const float*)d_in[14];
    const float* whhb = (const float*)d_in[15];
    const float* bihb = (const float*)d_in[16];
    const float* bhhb = (const float*)d_in[17];

    float *buf0, *buf1, *buf2, *buf3, *buf4, *xbuf, *gxbuf, *wcat, *bcat, *hA, *hB;
    cudaGetSymbolAddress((void**)&buf0, g_buf0);
    cudaGetSymbolAddress((void**)&buf1, g_buf1);
    cudaGetSymbolAddress((void**)&buf2, g_buf2);
    cudaGetSymbolAddress((void**)&buf3, g_buf3);
    cudaGetSymbolAddress((void**)&buf4, g_buf4);
    cudaGetSymbolAddress((void**)&xbuf, g_x);
    cudaGetSymbolAddress((void**)&gxbuf, g_gx);
    cudaGetSymbolAddress((void**)&wcat, g_wcat);
    cudaGetSymbolAddress((void**)&bcat, g_bcat);
    cudaGetSymbolAddress((void**)&hA, g_hA);
    cudaGetSymbolAddress((void**)&hB, g_hB);

    float* out     = (float*)d_out;
    float* hid_out = out + (size_t)BATCH * T_STEPS * 512;

    // CNN front-end
    conv3x3_relu<1, 8, 80, 4, 480><<<dim3(120, 64), dim3(80, 4)>>>(img, c0w, c0b, buf0);
    conv3x3_relu<8, 16, 80, 4, 480><<<dim3(120, 64), dim3(80, 4)>>>(buf0, c1w, c1b, buf1);
    {
        int total = 64 * 16 * 160 * 40;
        pool1_kernel<<<(total + 255) / 256, 256>>>(buf1, buf2);
    }
    conv3x3_relu<16, 16, 40, 8, 160><<<dim3(20, 64), dim3(40, 8)>>>(buf2, c2w, c2b, buf3);
    conv3x3_relu<16, 32, 40, 8, 160><<<dim3(20, 64), dim3(40, 8)>>>(buf3, c3w, c3b, buf4);
    {
        int total = 64 * 32 * 40 * 20;
        pool2t_kernel<<<(total + 255) / 256, 256>>>(buf4, xbuf);
    }

    // GRU input gates (both directions in one GEMM)
    {
        int total = GX_N * I_GRU;
        prep_w_kernel<<<(total + 255) / 256, 256>>>(wihf, wihb, bihf, bihb, wcat, bcat);
    }
    gemm_nt_kernel<<<dim3(GX_N / 64, (T_STEPS * BATCH) / 64), 256>>>(xbuf, wcat, bcat, gxbuf);

    // GRU recurrence
    init_h_kernel<<<(2 * BATCH * HID + 255) / 256, 256>>>(hid0, hA);
    for (int s = 0; s < T_STEPS; s++) {
        float* hin  = (s & 1) ? hB : hA;
        float* hout = (s & 1) ? hA : hB;
        gru_step_kernel<<<128, 256>>>(gxbuf, whhf, whhb, bhhf, bhhb,
                                      hin, hout, out, hid_out, s);
    }
}

// round 16
// speedup vs baseline: 1.0612x; 1.0612x over previous
#include <cuda_runtime.h>
#include <cstdint>

// ---------------------------------------------------------------------------
// Problem constants
// ---------------------------------------------------------------------------
#define BATCH 64
#define HID 256
#define T_STEPS 40
#define I_GRU 640           // 20 * 32
#define G3 768              // 3*HID
#define GX_N 1536           // both directions

// ---------------------------------------------------------------------------
// Scratch (static device allocations — no cudaMalloc anywhere)
// ---------------------------------------------------------------------------
__device__ float g_buf2[64 * 16 * 160 * 40];        // fused conv0/conv1/pool1 out
__device__ float g_buf3[64 * 16 * 160 * 40];        // conv2 out
__device__ float g_x   [T_STEPS * BATCH * I_GRU];   // GRU input (T,B,I)
__device__ float g_gx  [T_STEPS * BATCH * GX_N];    // precomputed input gates
__device__ float g_wcat[GX_N * I_GRU];              // concat(w_ih_f, w_ih_b)
__device__ float g_bcat[GX_N];
__device__ float g_hA  [2 * BATCH * HID];
__device__ float g_hB  [2 * BATCH * HID];

// ---------------------------------------------------------------------------
// Fused conv0(1->8) + ReLU + conv1(8->16) + ReLU + maxpool(3,2)
//   input  (64,1,480,80)  ->  output (64,16,160,40)
// Block: (80,4) threads, 12 conv1 rows per block (VY=3 rows/thread = one pool
// window), conv0 recomputed into smem with halo. Pool cols via warp shuffle.
// ---------------------------------------------------------------------------
__global__ void __launch_bounds__(320, 2)
conv01_pool_kernel(const float* __restrict__ img,
                   const float* __restrict__ w0, const float* __restrict__ b0c,
                   const float* __restrict__ w1, const float* __restrict__ b1c,
                   float* __restrict__ outp)
{
    __shared__ __align__(16) float sIn0[16][84];      // rows h0-2..h0+13, cols -2..81
    __shared__ __align__(16) float sMid[8][14][82];   // conv0+relu, rows h0-1..h0+12
    __shared__ __align__(16) float sW1[72][16];
    __shared__ __align__(16) float sW0[9][8];
    __shared__ float sB0[8];
    __shared__ float sB1[16];

    const int tx  = threadIdx.x;          // 0..79
    const int ty  = threadIdx.y;          // 0..3
    const int tid = ty * 80 + tx;
    const int b   = blockIdx.y;
    const int h0  = blockIdx.x * 12;

    // weights
    for (int i = tid; i < 72 * 16; i += 320) {
        int co = i % 16, tap = i / 16;
        int ci = tap / 9, t9 = tap % 9;
        sW1[tap][co] = w1[(co * 8 + ci) * 9 + t9];
    }
    if (tid < 72) { int co = tid % 8, t9 = tid / 8; sW0[t9][co] = w0[co * 9 + t9]; }
    if (tid < 16) sB1[tid] = b1c[tid];
    if (tid >= 16 && tid < 24) sB0[tid - 16] = b0c[tid - 16];

    // raw input tile (zero padded)
    for (int i = tid; i < 16 * 84; i += 320) {
        int c = i % 84, r = i / 84;
        int gh = h0 - 2 + r, gw = c - 2;
        float v = 0.f;
        if (gh >= 0 && gh < 480 && gw >= 0 && gw < 80)
            v = img[(size_t)b * (480 * 80) + gh * 80 + gw];
        sIn0[r][c] = v;
    }
    __syncthreads();

    // conv0 + relu into sMid (zero for out-of-range positions = conv1 padding)
    for (int i = tid; i < 14 * 82; i += 320) {
        int c = i % 82, r = i / 82;
        int gh = h0 - 1 + r, gw = c - 1;
        if (gh >= 0 && gh < 480 && gw >= 0 && gw < 80) {
            float a[8];
#pragma unroll
            for (int co = 0; co < 8; co++) a[co] = sB0[co];
#pragma unroll
            for (int dy = 0; dy < 3; dy++)
#pragma unroll
                for (int dx = 0; dx < 3; dx++) {
                    float v = sIn0[r + dy][c + dx];
#pragma unroll
                    for (int co = 0; co < 8; co++)
                        a[co] = fmaf(v, sW0[dy * 3 + dx][co], a[co]);
                }
#pragma unroll
            for (int co = 0; co < 8; co++) sMid[co][r][c] = fmaxf(a[co], 0.f);
        } else {
#pragma unroll
            for (int co = 0; co < 8; co++) sMid[co][r][c] = 0.f;
        }
    }
    __syncthreads();

    // conv1: 3 rows per thread (one pool window), all 16 channels in registers
    float acc[3][16];
#pragma unroll
    for (int vy = 0; vy < 3; vy++)
#pragma unroll
        for (int co = 0; co < 16; co++) acc[vy][co] = sB1[co];

#pragma unroll
    for (int ci = 0; ci < 8; ci++) {
#pragma unroll
        for (int kx = 0; kx < 3; kx++) {
            float v[5];
#pragma unroll
            for (int r = 0; r < 5; r++) v[r] = sMid[ci][ty * 3 + r][tx + kx];
#pragma unroll
            for (int ky = 0; ky < 3; ky++) {
                const float4* wv = (const float4*)&sW1[ci * 9 + ky * 3 + kx][0];
#pragma unroll
                for (int q = 0; q < 4; q++) {
                    float4 w4 = wv[q];
#pragma unroll
                    for (int vy = 0; vy < 3; vy++) {
                        float x = v[vy + ky];
                        acc[vy][q * 4 + 0] = fmaf(x, w4.x, acc[vy][q * 4 + 0]);
                        acc[vy][q * 4 + 1] = fmaf(x, w4.y, acc[vy][q * 4 + 1]);
                        acc[vy][q * 4 + 2] = fmaf(x, w4.z, acc[vy][q * 4 + 2]);
                        acc[vy][q * 4 + 3] = fmaf(x, w4.w, acc[vy][q * 4 + 3]);
                    }
                }
            }
        }
    }

    // relu + pool 3 rows (register) x 2 cols (shuffle)
    float m[16];
#pragma unroll
    for (int co = 0; co < 16; co++) {
        float t0 = fmaxf(fmaxf(acc[0][co], acc[1][co]), acc[2][co]);
        t0 = fmaxf(t0, 0.f);
        m[co] = fmaxf(t0, __shfl_down_sync(0xffffffffu, t0, 1));
    }
    if ((tx & 1) == 0) {
        int wo = tx >> 1;                       // 0..39
        int ho = blockIdx.x * 4 + ty;           // 0..159
        float* dst = outp + ((size_t)(b * 16) * 160 + ho) * 40 + wo;
#pragma unroll
        for (int co = 0; co < 16; co++) dst[(size_t)co * 6400] = m[co];
    }
}

// ---------------------------------------------------------------------------
// conv2: 16->16 on (160,40), ReLU. Block (40,8), VY=4 rows/thread (TH=32).
// Dynamic smem: sIn[16][34][42] + sW[144][16] + sB[16]  (~100.7 KB)
// ---------------------------------------------------------------------------
#define C23_SIN (16 * 34 * 42)
#define C23_SMEM ((C23_SIN + 144 * 16 + 16) * 4)

__global__ void __launch_bounds__(320, 2)
conv2_kernel(const float* __restrict__ in, const float* __restrict__ wgt,
             const float* __restrict__ bias, float* __restrict__ outp)
{
    extern __shared__ __align__(16) float sm[];
    float* sIn = sm;                   // [(ci*34 + r)*42 + c]
    float* sW  = sm + C23_SIN;         // [tap*16 + co]
    float* sB  = sW + 144 * 16;

    const int tx  = threadIdx.x;       // 0..39
    const int ty  = threadIdx.y;       // 0..7
    const int tid = ty * 40 + tx;
    const int b   = blockIdx.y;
    const int h0  = blockIdx.x * 32;

    for (int i = tid; i < 144 * 16; i += 320) {
        int co = i % 16, tap = i / 16;
        int ci = tap / 9, t9 = tap % 9;
        sW[tap * 16 + co] = wgt[(co * 16 + ci) * 9 + t9];
    }
    if (tid < 16) sB[tid] = bias[tid];

    for (int i = tid; i < C23_SIN; i += 320) {
        int c = i % 42, r = (i / 42) % 34, ci = i / (42 * 34);
        int gh = h0 - 1 + r, gw = c - 1;
        float v = 0.f;
        if (gh >= 0 && gh < 160 && gw >= 0 && gw < 40)
            v = in[((size_t)(b * 16 + ci) * 160 + gh) * 40 + gw];
        sIn[i] = v;
    }
    __syncthreads();

    float acc[4][16];
#pragma unroll
    for (int vy = 0; vy < 4; vy++)
#pragma unroll
        for (int co = 0; co < 16; co++) acc[vy][co] = sB[co];

#pragma unroll
    for (int ci = 0; ci < 16; ci++) {
#pragma unroll
        for (int kx = 0; kx < 3; kx++) {
            float v[6];
#pragma unroll
            for (int r = 0; r < 6; r++)
                v[r] = sIn[(ci * 34 + ty * 4 + r) * 42 + tx + kx];
#pragma unroll
            for (int ky = 0; ky < 3; ky++) {
                const float4* wv = (const float4*)&sW[(ci * 9 + ky * 3 + kx) * 16];
#pragma unroll
                for (int q = 0; q < 4; q++) {
                    float4 w4 = wv[q];
#pragma unroll
                    for (int vy = 0; vy < 4; vy++) {
                        float x = v[vy + ky];
                        acc[vy][q * 4 + 0] = fmaf(x, w4.x, acc[vy][q * 4 + 0]);
                        acc[vy][q * 4 + 1] = fmaf(x, w4.y, acc[vy][q * 4 + 1]);
                        acc[vy][q * 4 + 2] = fmaf(x, w4.z, acc[vy][q * 4 + 2]);
                        acc[vy][q * 4 + 3] = fmaf(x, w4.w, acc[vy][q * 4 + 3]);
                    }
                }
            }
        }
    }

#pragma unroll
    for (int vy = 0; vy < 4; vy++) {
        int gh = h0 + ty * 4 + vy;
#pragma unroll
        for (int co = 0; co < 16; co++)
            outp[((size_t)(b * 16 + co) * 160 + gh) * 40 + tx] =
                fmaxf(acc[vy][co], 0.f);
    }
}

// ---------------------------------------------------------------------------
// conv3: 16->32 on (160,40), ReLU, fused maxpool(4,2) + transpose to GRU x.
// COUT split into 2 halves via blockIdx.z (16 channels each). Block (40,8),
// VY=4 rows/thread = exactly one pool window. Output x[t][b][w*32 + c].
// ---------------------------------------------------------------------------
__global__ void __launch_bounds__(320, 2)
conv3_poolt_kernel(const float* __restrict__ in, const float* __restrict__ wgt,
                   const float* __restrict__ bias, float* __restrict__ xout)
{
    extern __shared__ __align__(16) float sm[];
    float* sIn = sm;
    float* sW  = sm + C23_SIN;
    float* sB  = sW + 144 * 16;

    const int tx  = threadIdx.x;       // 0..39
    const int ty  = threadIdx.y;       // 0..7
    const int tid = ty * 40 + tx;
    const int b   = blockIdx.y;
    const int h0  = blockIdx.x * 32;
    const int z   = blockIdx.z;        // 0/1 channel half
    const int cb  = z * 16;

    for (int i = tid; i < 144 * 16; i += 320) {
        int co = i % 16, tap = i / 16;
        int ci = tap / 9, t9 = tap % 9;
        sW[tap * 16 + co] = wgt[((cb + co) * 16 + ci) * 9 + t9];
    }
    if (tid < 16) sB[tid] = bias[cb + tid];

    for (int i = tid; i < C23_SIN; i += 320) {
        int c = i % 42, r = (i / 42) % 34, ci = i / (42 * 34);
        int gh = h0 - 1 + r, gw = c - 1;
        float v = 0.f;
        if (gh >= 0 && gh < 160 && gw >= 0 && gw < 40)
            v = in[((size_t)(b * 16 + ci) * 160 + gh) * 40 + gw];
        sIn[i] = v;
    }
    __syncthreads();

    float acc[4][16];
#pragma unroll
    for (int vy = 0; vy < 4; vy++)
#pragma unroll
        for (int co = 0; co < 16; co++) acc[vy][co] = sB[co];

#pragma unroll
    for (int ci = 0; ci < 16; ci++) {
#pragma unroll
        for (int kx = 0; kx < 3; kx++) {
            float v[6];
#pragma unroll
            for (int r = 0; r < 6; r++)
                v[r] = sIn[(ci * 34 + ty * 4 + r) * 42 + tx + kx];
#pragma unroll
            for (int ky = 0; ky < 3; ky++) {
                const float4* wv = (const float4*)&sW[(ci * 9 + ky * 3 + kx) * 16];
#pragma unroll
                for (int q = 0; q < 4; q++) {
                    float4 w4 = wv[q];
#pragma unroll
                    for (int vy = 0; vy < 4; vy++) {
                        float x = v[vy + ky];
                        acc[vy][q * 4 + 0] = fmaf(x, w4.x, acc[vy][q * 4 + 0]);
                        acc[vy][q * 4 + 1] = fmaf(x, w4.y, acc[vy][q * 4 + 1]);
                        acc[vy][q * 4 + 2] = fmaf(x, w4.z, acc[vy][q * 4 + 2]);
                        acc[vy][q * 4 + 3] = fmaf(x, w4.w, acc[vy][q * 4 + 3]);
                    }
                }
            }
        }
    }

    // relu + pool 4 rows (register) x 2 cols (shuffle), then transposed store
    float m[16];
#pragma unroll
    for (int co = 0; co < 16; co++) {
        float t0 = fmaxf(fmaxf(acc[0][co], acc[1][co]),
                         fmaxf(acc[2][co], acc[3][co]));
        t0 = fmaxf(t0, 0.f);
        m[co] = fmaxf(t0, __shfl_down_sync(0xffffffffu, t0, 1));
    }
    if ((tx & 1) == 0) {
        int w = tx >> 1;                        // 0..19
        int t = blockIdx.x * 8 + ty;            // 0..39
        float* dst = xout + ((size_t)(t * BATCH + b)) * I_GRU + w * 32 + cb;
        float4* d4 = (float4*)dst;
        d4[0] = make_float4(m[0],  m[1],  m[2],  m[3]);
        d4[1] = make_float4(m[4],  m[5],  m[6],  m[7]);
        d4[2] = make_float4(m[8],  m[9],  m[10], m[11]);
        d4[3] = make_float4(m[12], m[13], m[14], m[15]);
    }
}

// ---------------------------------------------------------------------------
// Concatenate input-gate weights/biases for both directions.
// ---------------------------------------------------------------------------
__global__ void prep_w_kernel(const float* __restrict__ wf, const float* __restrict__ wb,
                              const float* __restrict__ bf, const float* __restrict__ bb,
                              float* __restrict__ wcat, float* __restrict__ bcat)
{
    int i = blockIdx.x * blockDim.x + threadIdx.x;
    const int total = GX_N * I_GRU;
    if (i < total)
        wcat[i] = (i < G3 * I_GRU) ? wf[i] : wb[i - G3 * I_GRU];
    if (i < GX_N)
        bcat[i] = (i < G3) ? bf[i] : bb[i - G3];
}

__global__ void init_h_kernel(const float* __restrict__ h0, float* __restrict__ h)
{
    int i = blockIdx.x * blockDim.x + threadIdx.x;
    if (i < 2 * BATCH * HID) h[i] = h0[i];
}

// ---------------------------------------------------------------------------
// gx = x @ Wcat^T + bcat   (M=2560, N=1536, K=640, NT)
// 128x64 tile, 256 threads, 8x4 microtile, register-prefetch double buffer.
// ---------------------------------------------------------------------------
__global__ void gemm_nt_v2(const float* __restrict__ A,   // (2560, 640)
                           const float* __restrict__ B,   // (1536, 640)
                           const float* __restrict__ bias,
                           float* __restrict__ C)         // (2560, 1536)
{
    __shared__ __align__(16) float As[16][132];
    __shared__ __align__(16) float Bs[16][68];

    const int t  = threadIdx.x;       // 0..255
    const int bm = blockIdx.y;        // 0..19
    const int bn = blockIdx.x;        // 0..23
    const int m0 = (t >> 4) * 8;      // 0..120
    const int n0 = (t & 15) * 4;      // 0..60

    const int ar0 = t >> 2;           // 0..63
    const int ak  = (t & 3) * 4;      // 0,4,8,12

    const float* Aptr0 = A + (size_t)(bm * 128 + ar0) * I_GRU + ak;
    const float* Aptr1 = Aptr0 + (size_t)64 * I_GRU;
    const float* Bptr  = B + (size_t)(bn * 64 + ar0) * I_GRU + ak;

    float4 pa0 = *(const float4*)Aptr0;
    float4 pa1 = *(const float4*)Aptr1;
    float4 pb  = *(const float4*)Bptr;

    float acc[8][4] = {};

    for (int k0 = 0; k0 < I_GRU; k0 += 16) {
        As[ak + 0][ar0] = pa0.x; As[ak + 1][ar0] = pa0.y;
        As[ak + 2][ar0] = pa0.z; As[ak + 3][ar0] = pa0.w;
        As[ak + 0][ar0 + 64] = pa1.x; As[ak + 1][ar0 + 64] = pa1.y;
        As[ak + 2][ar0 + 64] = pa1.z; As[ak + 3][ar0 + 64] = pa1.w;
        Bs[ak + 0][ar0] = pb.x; Bs[ak + 1][ar0] = pb.y;
        Bs[ak + 2][ar0] = pb.z; Bs[ak + 3][ar0] = pb.w;
        __syncthreads();

        if (k0 + 16 < I_GRU) {
            pa0 = *(const float4*)(Aptr0 + k0 + 16);
            pa1 = *(const float4*)(Aptr1 + k0 + 16);
            pb  = *(const float4*)(Bptr  + k0 + 16);
        }

#pragma unroll
        for (int k = 0; k < 16; k++) {
            float4 a0 = *(const float4*)&As[k][m0];
            float4 a1 = *(const float4*)&As[k][m0 + 4];
            float4 bq = *(const float4*)&Bs[k][n0];
            acc[0][0] = fmaf(a0.x, bq.x, acc[0][0]);
            acc[0][1] = fmaf(a0.x, bq.y, acc[0][1]);
            acc[0][2] = fmaf(a0.x, bq.z, acc[0][2]);
            acc[0][3] = fmaf(a0.x, bq.w, acc[0][3]);
            acc[1][0] = fmaf(a0.y, bq.x, acc[1][0]);
            acc[1][1] = fmaf(a0.y, bq.y, acc[1][1]);
            acc[1][2] = fmaf(a0.y, bq.z, acc[1][2]);
            acc[1][3] = fmaf(a0.y, bq.w, acc[1][3]);
            acc[2][0] = fmaf(a0.z, bq.x, acc[2][0]);
            acc[2][1] = fmaf(a0.z, bq.y, acc[2][1]);
            acc[2][2] = fmaf(a0.z, bq.z, acc[2][2]);
            acc[2][3] = fmaf(a0.z, bq.w, acc[2][3]);
            acc[3][0] = fmaf(a0.w, bq.x, acc[3][0]);
            acc[3][1] = fmaf(a0.w, bq.y, acc[3][1]);
            acc[3][2] = fmaf(a0.w, bq.z, acc[3][2]);
            acc[3][3] = fmaf(a0.w, bq.w, acc[3][3]);
            acc[4][0] = fmaf(a1.x, bq.x, acc[4][0]);
            acc[4][1] = fmaf(a1.x, bq.y, acc[4][1]);
            acc[4][2] = fmaf(a1.x, bq.z, acc[4][2]);
            acc[4][3] = fmaf(a1.x, bq.w, acc[4][3]);
            acc[5][0] = fmaf(a1.y, bq.x, acc[5][0]);
            acc[5][1] = fmaf(a1.y, bq.y, acc[5][1]);
            acc[5][2] = fmaf(a1.y, bq.z, acc[5][2]);
            acc[5][3] = fmaf(a1.y, bq.w, acc[5][3]);
            acc[6][0] = fmaf(a1.z, bq.x, acc[6][0]);
            acc[6][1] = fmaf(a1.z, bq.y, acc[6][1]);
            acc[6][2] = fmaf(a1.z, bq.z, acc[6][2]);
            acc[6][3] = fmaf(a1.z, bq.w, acc[6][3]);
            acc[7][0] = fmaf(a1.w, bq.x, acc[7][0]);
            acc[7][1] = fmaf(a1.w, bq.y, acc[7][1]);
            acc[7][2] = fmaf(a1.w, bq.z, acc[7][2]);
            acc[7][3] = fmaf(a1.w, bq.w, acc[7][3]);
        }
        __syncthreads();
    }

    const int cm = bm * 128 + m0;
    const int cn = bn * 64 + n0;
    float4 bb = *(const float4*)(bias + cn);
#pragma unroll
    for (int i = 0; i < 8; i++) {
        float4 r;
        r.x = acc[i][0] + bb.x;
        r.y = acc[i][1] + bb.y;
        r.z = acc[i][2] + bb.z;
        r.w = acc[i][3] + bb.w;
        *(float4*)(C + (size_t)(cm + i) * GX_N + cn) = r;
    }
}

// ---------------------------------------------------------------------------
// One GRU time step, both directions fused (unchanged from passing version).
// ---------------------------------------------------------------------------
__global__ void gru_step_kernel(const float* __restrict__ gx,
                                const float* __restrict__ whh_f,
                                const float* __restrict__ whh_b,
                                const float* __restrict__ bhh_f,
                                const float* __restrict__ bhh_b,
                                const float* __restrict__ h_in,
                                float* __restrict__ h_out,
                                float* __restrict__ outp,      // (B,T,512)
                                float* __restrict__ hid_out,   // (2,B,256)
                                int step)
{
    const int x   = blockIdx.x;      // 0..127
    const int dir = x >> 6;
    const int rem = x & 63;
    const int bg  = rem >> 3;        // 0..7
    const int jg  = rem & 7;         // 0..7
    const int tid = threadIdx.x;
    const int bl  = tid >> 5;        // 0..7
    const int jl  = tid & 31;
    const int b   = bg * 8 + bl;
    const int j   = jg * 32 + jl;

    __shared__ __align__(16) float sh[8][HID];
    const float* hbase = h_in + (size_t)dir * BATCH * HID + (size_t)bg * 8 * HID;
    for (int i = tid; i < 8 * HID; i += 256)
        sh[i >> 8][i & 255] = hbase[i];
    __syncthreads();

    const float* whh = dir ? whh_b : whh_f;
    const float* bhh = dir ? bhh_b : bhh_f;

    const float4* hv = (const float4*)sh[bl];
    const float4* wr = (const float4*)(whh + (size_t)j * HID);
    const float4* wz = (const float4*)(whh + (size_t)(j + 256) * HID);
    const float4* wn = (const float4*)(whh + (size_t)(j + 512) * HID);

    float ar = 0.f, az = 0.f, an = 0.f;
#pragma unroll 8
    for (int k = 0; k < HID / 4; k++) {
        float4 h4 = hv[k];
        float4 r4 = wr[k];
        float4 z4 = wz[k];
        float4 n4 = wn[k];
        ar = fmaf(h4.x, r4.x, ar); ar = fmaf(h4.y, r4.y, ar);
        ar = fmaf(h4.z, r4.z, ar); ar = fmaf(h4.w, r4.w, ar);
        az = fmaf(h4.x, z4.x, az); az = fmaf(h4.y, z4.y, az);
        az = fmaf(h4.z, z4.z, az); az = fmaf(h4.w, z4.w, az);
        an = fmaf(h4.x, n4.x, an); an = fmaf(h4.y, n4.y, an);
        an = fmaf(h4.z, n4.z, an); an = fmaf(h4.w, n4.w, an);
    }

    const int t = dir ? (T_STEPS - 1 - step) : step;
    const float* gxr = gx + (size_t)(t * BATCH + b) * GX_N + dir * G3;
    float xr = gxr[j];
    float xz = gxr[256 + j];
    float xn = gxr[512 + j];

    float hr = ar + bhh[j];
    float hz = az + bhh[256 + j];
    float hn = an + bhh[512 + j];

    float r = 1.f / (1.f + __expf(-(xr + hr)));
    float z = 1.f / (1.f + __expf(-(xz + hz)));
    float n = tanhf(xn + r * hn);

    float hold = sh[bl][j];
    float hnew = (1.f - z) * n + z * hold;

    h_out[(size_t)dir * BATCH * HID + (size_t)b * HID + j] = hnew;
    outp[((size_t)b * T_STEPS + t) * 512 + dir * HID + j] = hnew;
    if (step == T_STEPS - 1)
        hid_out[(size_t)dir * BATCH * HID + (size_t)b * HID + j] = hnew;
}

// ---------------------------------------------------------------------------
// Launch
// ---------------------------------------------------------------------------
extern "C" void kernel_launch(void* const* d_in, const int* in_sizes, int n_in,
                              void* d_out, int out_size)
{
    const float* img  = (const float*)d_in[0];
    const float* hid0 = (const float*)d_in[1];
    const float* c0w  = (const float*)d_in[2];
    const float* c0b  = (const float*)d_in[3];
    const float* c1w  = (const float*)d_in[4];
    const float* c1b  = (const float*)d_in[5];
    const float* c2w  = (const float*)d_in[6];
    const float* c2b  = (const float*)d_in[7];
    const float* c3w  = (const float*)d_in[8];
    const float* c3b  = (const float*)d_in[9];
    const float* wihf = (const float*)d_in[10];
    const float* whhf = (const float*)d_in[11];
    const float* bihf = (const float*)d_in[12];
    const float* bhhf = (const float*)d_in[13];
    const float* wihb = (const float*)d_in[14];
    const float* whhb = (const float*)d_in[15];
    const float* bihb = (const float*)d_in[16];
    const float* bhhb = (const float*)d_in[17];

    float *buf2, *buf3, *xbuf, *gxbuf, *wcat, *bcat, *hA, *hB;
    cudaGetSymbolAddress((void**)&buf2, g_buf2);
    cudaGetSymbolAddress((void**)&buf3, g_buf3);
    cudaGetSymbolAddress((void**)&xbuf, g_x);
    cudaGetSymbolAddress((void**)&gxbuf, g_gx);
    cudaGetSymbolAddress((void**)&wcat, g_wcat);
    cudaGetSymbolAddress((void**)&bcat, g_bcat);
    cudaGetSymbolAddress((void**)&hA, g_hA);
    cudaGetSymbolAddress((void**)&hB, g_hB);

    float* out     = (float*)d_out;
    float* hid_out = out + (size_t)BATCH * T_STEPS * 512;

    // allow >48KB dynamic smem for conv2/conv3 (host-side, capture-safe)
    cudaFuncSetAttribute(conv2_kernel,
                         cudaFuncAttributeMaxDynamicSharedMemorySize, C23_SMEM);
    cudaFuncSetAttribute(conv3_poolt_kernel,
                         cudaFuncAttributeMaxDynamicSharedMemorySize, C23_SMEM);

    // CNN front-end (conv0+conv1+pool1 fused; conv3+pool2+transpose fused)
    conv01_pool_kernel<<<dim3(40, 64), dim3(80, 4)>>>(img, c0w, c0b, c1w, c1b, buf2);
    conv2_kernel<<<dim3(5, 64), dim3(40, 8), C23_SMEM>>>(buf2, c2w, c2b, buf3);
    conv3_poolt_kernel<<<dim3(5, 64, 2), dim3(40, 8), C23_SMEM>>>(buf3, c3w, c3b, xbuf);

    // GRU input gates (both directions in one GEMM)
    {
        int total = GX_N * I_GRU;
        prep_w_kernel<<<(total + 255) / 256, 256>>>(wihf, wihb, bihf, bihb, wcat, bcat);
    }
    gemm_nt_v2<<<dim3(GX_N / 64, (T_STEPS * BATCH) / 128), 256>>>(xbuf, wcat, bcat, gxbuf);

    // GRU recurrence
    init_h_kernel<<<(2 * BATCH * HID + 255) / 256, 256>>>(hid0, hA);
    for (int s = 0; s < T_STEPS; s++) {
        float* hin  = (s & 1) ? hB : hA;
        float* hout = (s & 1) ? hA : hB;
        gru_step_kernel<<<128, 256>>>(gxbuf, whhf, whhb, bhhf, bhhb,
                                      hin, hout, out, hid_out, s);
    }
}